// round 15
// baseline (speedup 1.0000x reference)
#include <cuda_runtime.h>
#include <cstdint>

typedef unsigned long long ull;

#define BB 2
#define NN 768
#define CS 768
#define HH 16
#define HD 48
#define CZ 128

#define IT 64      // attention i-tile rows
#define JT 64      // attention j-tile cols
#define PSS 68     // P tile row stride (pad for banks, keeps 8B align)
#define WSP 140    // padded Ws row stride: col' = c + (c>>5)*4, conflict-free

// ----- scratch (static device globals: no allocation allowed) -----
__device__ float g_q [BB*NN*CS];
__device__ float g_k [BB*NN*CS];
__device__ float g_v [BB*NN*CS];
__device__ float g_g [BB*NN*CS];
__device__ float g_og[BB*NN*CS];
__device__ float g_bias[(size_t)BB*HH*NN*NN];

// ----- packed f32x2 helpers -----
__device__ __forceinline__ ull pack2(float x, float y) {
    ull r; asm("mov.b64 %0, {%1, %2};" : "=l"(r) : "f"(x), "f"(y)); return r;
}
__device__ __forceinline__ ull dup2(float x) { return pack2(x, x); }
__device__ __forceinline__ void fma2(ull& d, ull a, ull b) {
    asm("fma.rn.f32x2 %0, %1, %2, %0;" : "+l"(d) : "l"(a), "l"(b));
}
__device__ __forceinline__ void mul2(ull& d, ull a) {
    asm("mul.rn.f32x2 %0, %0, %1;" : "+l"(d) : "l"(a));
}
__device__ __forceinline__ void unpack2(ull v, float& x, float& y) {
    asm("mov.b64 {%0, %1}, %2;" : "=f"(x), "=f"(y) : "l"(v));
}

// ----- 128x128 tiled GEMM, BK=16, 256 threads, 8x8/thread, double-buffered,
// Ws columns padded (c' = c + (c>>5)*4) for conflict-free stride-8 LDS.128. --
__device__ __forceinline__ void gemm_block(
    const float* __restrict__ A, const float* __restrict__ W,
    const float* __restrict__ bvec, float* __restrict__ C, int act,
    int m0, int n0, int kbeg, int ktiles)
{
    __shared__ __align__(16) float As[2][16][128];
    __shared__ __align__(16) float Ws[2][16][WSP];
    const int tid = threadIdx.x;
    const int lr = tid >> 1;
    const int lq = (tid & 1) * 8;
    const int tx = tid & 15, ty = tid >> 4;
    const int lrp = lr + ((lr >> 5) << 2);          // padded write col
    const int txp = tx * 8 + ((tx >> 2) << 2);      // padded read col

    const float* ap = A + (size_t)(m0 + lr) * CS + kbeg + lq;
    const float* wp = W + (size_t)(n0 + lr) * CS + kbeg + lq;

    ull acc[8][4];
#pragma unroll
    for (int i = 0; i < 8; i++)
#pragma unroll
        for (int j = 0; j < 4; j++) acc[i][j] = 0ULL;

    float4 a0 = *(const float4*)ap;
    float4 a1 = *(const float4*)(ap + 4);
    float4 w0 = *(const float4*)wp;
    float4 w1 = *(const float4*)(wp + 4);

    for (int kt = 0; kt < ktiles; kt++) {
        const int buf = kt & 1;
        As[buf][lq+0][lr]=a0.x; As[buf][lq+1][lr]=a0.y;
        As[buf][lq+2][lr]=a0.z; As[buf][lq+3][lr]=a0.w;
        As[buf][lq+4][lr]=a1.x; As[buf][lq+5][lr]=a1.y;
        As[buf][lq+6][lr]=a1.z; As[buf][lq+7][lr]=a1.w;
        Ws[buf][lq+0][lrp]=w0.x; Ws[buf][lq+1][lrp]=w0.y;
        Ws[buf][lq+2][lrp]=w0.z; Ws[buf][lq+3][lrp]=w0.w;
        Ws[buf][lq+4][lrp]=w1.x; Ws[buf][lq+5][lrp]=w1.y;
        Ws[buf][lq+6][lrp]=w1.z; Ws[buf][lq+7][lrp]=w1.w;
        __syncthreads();

        if (kt + 1 < ktiles) {                  // prefetch next k-tile
            const int ko = (kt + 1) * 16;
            a0 = *(const float4*)(ap + ko);
            a1 = *(const float4*)(ap + ko + 4);
            w0 = *(const float4*)(wp + ko);
            w1 = *(const float4*)(wp + ko + 4);
        }

#pragma unroll
        for (int k = 0; k < 16; k++) {
            float4 fa0 = *(const float4*)&As[buf][k][ty*8];
            float4 fa1 = *(const float4*)&As[buf][k][ty*8+4];
            ulonglong2 b01 = *(const ulonglong2*)&Ws[buf][k][txp];
            ulonglong2 b23 = *(const ulonglong2*)&Ws[buf][k][txp+4];
            float av[8] = {fa0.x,fa0.y,fa0.z,fa0.w,fa1.x,fa1.y,fa1.z,fa1.w};
#pragma unroll
            for (int i = 0; i < 8; i++) {
                ull ad = dup2(av[i]);
                fma2(acc[i][0], ad, b01.x);
                fma2(acc[i][1], ad, b01.y);
                fma2(acc[i][2], ad, b23.x);
                fma2(acc[i][3], ad, b23.y);
            }
        }
        // no trailing barrier: next STS targets the other buffer.
    }

    float bv[8];
    if (bvec) {
        float4 b0 = *(const float4*)&bvec[n0 + tx*8];
        float4 b1 = *(const float4*)&bvec[n0 + tx*8 + 4];
        bv[0]=b0.x; bv[1]=b0.y; bv[2]=b0.z; bv[3]=b0.w;
        bv[4]=b1.x; bv[5]=b1.y; bv[6]=b1.z; bv[7]=b1.w;
    } else {
#pragma unroll
        for (int c = 0; c < 8; c++) bv[c] = 0.f;
    }

#pragma unroll
    for (int i = 0; i < 8; i++) {
        float r[8];
#pragma unroll
        for (int j = 0; j < 4; j++) unpack2(acc[i][j], r[2*j], r[2*j+1]);
#pragma unroll
        for (int c = 0; c < 8; c++) {
            r[c] += bv[c];
            if (act) r[c] = 1.f / (1.f + __expf(-r[c]));
        }
        float* cp = C + (size_t)(m0 + ty*8 + i) * CS + n0 + tx*8;
        *(float4*)cp     = make_float4(r[0], r[1], r[2], r[3]);
        *(float4*)(cp+4) = make_float4(r[4], r[5], r[6], r[7]);
    }
}

// K1: q/k/v/g projections
__global__ void __launch_bounds__(256) qkvg_kernel(
    const float* __restrict__ s,  const float* __restrict__ kin,
    const float* __restrict__ Wq, const float* __restrict__ bq,
    const float* __restrict__ Wk, const float* __restrict__ Wv,
    const float* __restrict__ Wg)
{
    const float* A; const float* W; const float* bv = nullptr;
    float* C; int act = 0;
    switch (blockIdx.z) {
        case 0:  A = s;   W = Wq; bv = bq; C = g_q; break;
        case 1:  A = kin; W = Wk;          C = g_k; break;
        case 2:  A = kin; W = Wv;          C = g_v; break;
        default: A = s;   W = Wg;          C = g_g; act = 1; break;
    }
    gemm_block(A, W, bv, C, act, blockIdx.y * 128, blockIdx.x * 128, 0, CS/16);
}

// K4: out partials = og @ Wo^T over K-quarter, into dead q/k/v/g scratch.
__global__ void __launch_bounds__(256) outproj_partial_kernel(
    const float* __restrict__ Wo)
{
    float* part;
    switch (blockIdx.z) {
        case 0:  part = g_q; break;
        case 1:  part = g_k; break;
        case 2:  part = g_v; break;
        default: part = g_g; break;
    }
    gemm_block(g_og, Wo, nullptr, part, 0,
               blockIdx.y * 128, blockIdx.x * 128,
               blockIdx.z * (CS/4), (CS/4)/16);
}

// K5: out = p0+p1+p2+p3
__global__ void __launch_bounds__(256) reduce4_kernel(float* __restrict__ out)
{
    const int i = blockIdx.x * 256 + threadIdx.x;
    float4 a = ((const float4*)g_q)[i];
    float4 b = ((const float4*)g_k)[i];
    float4 c = ((const float4*)g_v)[i];
    float4 d = ((const float4*)g_g)[i];
    ((float4*)out)[i] = make_float4(a.x+b.x+c.x+d.x, a.y+b.y+c.y+d.y,
                                    a.z+b.z+c.z+d.z, a.w+b.w+c.w+d.w);
}

// K2: bias[b,h,i,j] = LayerNorm(z[b,i,j,:]) . Wz[h,:]  (coalesced via smem)
__global__ void __launch_bounds__(256) biasproj_kernel(
    const float* __restrict__ z,   const float* __restrict__ lng,
    const float* __restrict__ lnb, const float* __restrict__ Wz)
{
    __shared__ __align__(16) ull A2[128][8];
    __shared__ float Sf[16], Cf[16];
    __shared__ __align__(16) float zt[256][36];
    const int tid = threadIdx.x;
    if (tid < 128) {
        float gc = lng[tid];
#pragma unroll
        for (int h2 = 0; h2 < 8; h2++)
            A2[tid][h2] = pack2(gc * Wz[(2*h2)*CZ + tid], gc * Wz[(2*h2+1)*CZ + tid]);
    } else if (tid < 144) {
        int hh = tid - 128;
        float S = 0.f, Cc = 0.f;
        for (int c = 0; c < CZ; c++) {
            float w = Wz[hh*CZ + c];
            S  = fmaf(lng[c], w, S);
            Cc = fmaf(lnb[c], w, Cc);
        }
        Sf[hh] = S; Cf[hh] = Cc;
    }
    __syncthreads();

    const int row0 = blockIdx.x * 256;
    const int row  = row0 + tid;
    const int j = row % NN;
    const int t = row / NN;
    const int i = t % NN;
    const int b = t / NN;

    ull acc[8];
#pragma unroll
    for (int h2 = 0; h2 < 8; h2++) acc[h2] = 0ULL;
    float sum = 0.f, sumsq = 0.f;

    for (int ct = 0; ct < CZ/32; ct++) {
#pragma unroll
        for (int u = 0; u < 8; u++) {
            const int idx = u * 256 + tid;
            const int r = idx >> 3, q = idx & 7;
            *(float4*)&zt[r][q*4] =
                *(const float4*)&z[(size_t)(row0 + r)*CZ + ct*32 + q*4];
        }
        __syncthreads();

#pragma unroll
        for (int cq = 0; cq < 8; cq++) {
            float4 zv = *(const float4*)&zt[tid][cq*4];
            float zz[4] = {zv.x, zv.y, zv.z, zv.w};
#pragma unroll
            for (int u = 0; u < 4; u++) {
                const int c = ct*32 + cq*4 + u;
                float zc = zz[u];
                sum += zc;
                sumsq = fmaf(zc, zc, sumsq);
                ull zd = dup2(zc);
                const ulonglong2* ap = (const ulonglong2*)&A2[c][0];
                ulonglong2 a01 = ap[0], a23 = ap[1], a45 = ap[2], a67 = ap[3];
                fma2(acc[0], zd, a01.x); fma2(acc[1], zd, a01.y);
                fma2(acc[2], zd, a23.x); fma2(acc[3], zd, a23.y);
                fma2(acc[4], zd, a45.x); fma2(acc[5], zd, a45.y);
                fma2(acc[6], zd, a67.x); fma2(acc[7], zd, a67.y);
            }
        }
        __syncthreads();
    }

    const float inv = 1.f / CZ;
    float mu   = sum * inv;
    float var  = sumsq * inv - mu*mu;
    float rstd = rsqrtf(var + 1e-5f);

    const size_t base = ((size_t)b*HH*NN + i) * NN + j;
    const size_t hs   = (size_t)NN * NN;
#pragma unroll
    for (int h2 = 0; h2 < 8; h2++) {
        float d0, d1; unpack2(acc[h2], d0, d1);
        g_bias[base + (size_t)(2*h2)  *hs] = rstd*(d0 - mu*Sf[2*h2])   + Cf[2*h2];
        g_bias[base + (size_t)(2*h2+1)*hs] = rstd*(d1 - mu*Sf[2*h2+1]) + Cf[2*h2+1];
    }
}

__device__ __forceinline__ float shfl_max16(float v) {
    v = fmaxf(v, __shfl_xor_sync(0xffffffffu, v, 8));
    v = fmaxf(v, __shfl_xor_sync(0xffffffffu, v, 4));
    v = fmaxf(v, __shfl_xor_sync(0xffffffffu, v, 2));
    v = fmaxf(v, __shfl_xor_sync(0xffffffffu, v, 1));
    return v;
}
__device__ __forceinline__ float shfl_sum16(float v) {
    v += __shfl_xor_sync(0xffffffffu, v, 8);
    v += __shfl_xor_sync(0xffffffffu, v, 4);
    v += __shfl_xor_sync(0xffffffffu, v, 2);
    v += __shfl_xor_sync(0xffffffffu, v, 1);
    return v;
}

// K3: flash attention with pair bias + mask + gating (scores never hit HBM).
// R15: __launch_bounds__(256, 3) — regs capped at 80 so ALL 384 CTAs are
// resident in ONE wave (occ 2 ran 296 + 88 two-wave with a serial tail).
// Body = R12 (no prefetches; they bought nothing and cost ~40 regs).
__global__ void __launch_bounds__(256, 3) attn_kernel(const float* __restrict__ mask)
{
    extern __shared__ float sm[];
    float* qs = sm;                       // [48][64]
    float* ks = sm + 48*IT;               // [48][64]
    float* vs = ks + 48*JT;               // [64][48]
    float* ps = vs + JT*48;               // [64][PSS]
    float* scale_s = ps + IT*PSS;         // [64]
    float* l_s = scale_s + IT;            // [64]

    const int tid = threadIdx.x;
    const int h  = blockIdx.y & (HH-1);
    const int b  = blockIdx.y >> 4;
    const int i0 = blockIdx.x * IT;
    const int tx = tid & 15, ty = tid >> 4;   // S layout: 4 rows x 4 cols
    const int tx2 = tid & 7, ty2 = tid >> 3;  // PV layout: 2 rows x 6 cols

    for (int idx = tid; idx < IT * (HD/4); idx += 256) {
        const int r = idx / (HD/4), dq = idx % (HD/4);
        float4 v = *(const float4*)&g_q[((size_t)(b*NN + i0 + r))*CS + h*HD + dq*4];
        qs[(dq*4+0)*IT + r] = v.x; qs[(dq*4+1)*IT + r] = v.y;
        qs[(dq*4+2)*IT + r] = v.z; qs[(dq*4+3)*IT + r] = v.w;
    }

    float mrow[4] = {-1e30f, -1e30f, -1e30f, -1e30f};
    float lrow[4] = {0.f, 0.f, 0.f, 0.f};
    ull oacc[2][3];
#pragma unroll
    for (int r = 0; r < 2; r++)
#pragma unroll
        for (int c = 0; c < 3; c++) oacc[r][c] = 0ULL;

    const size_t bh = ((size_t)b*HH + h) * (size_t)NN * NN;
    const float scale = 0.14433756729740643f;

    for (int jt = 0; jt < NN / JT; jt++) {
        const int j0 = jt * JT;
        __syncthreads();

        for (int idx = tid; idx < JT * (HD/4); idx += 256) {
            const int j = idx / (HD/4), dq = idx % (HD/4);
            const size_t go = ((size_t)(b*NN + j0 + j))*CS + h*HD + dq*4;
            float4 kv = *(const float4*)&g_k[go];
            ks[(dq*4+0)*JT + j] = kv.x; ks[(dq*4+1)*JT + j] = kv.y;
            ks[(dq*4+2)*JT + j] = kv.z; ks[(dq*4+3)*JT + j] = kv.w;
            float4 vv = *(const float4*)&g_v[go];
            *(float4*)&vs[j*48 + dq*4] = vv;
        }
        __syncthreads();

        ull acc[4][2];
#pragma unroll
        for (int i = 0; i < 4; i++) { acc[i][0] = 0ULL; acc[i][1] = 0ULL; }

#pragma unroll 4
        for (int d = 0; d < HD; d++) {
            float4 a = *(const float4*)&qs[d*IT + ty*4];
            ulonglong2 kb = *(const ulonglong2*)&ks[d*JT + tx*4];
            float av[4] = {a.x, a.y, a.z, a.w};
#pragma unroll
            for (int i = 0; i < 4; i++) {
                ull ad = dup2(av[i]);
                fma2(acc[i][0], ad, kb.x);
                fma2(acc[i][1], ad, kb.y);
            }
        }

        float4 mk = *(const float4*)&mask[b*NN + j0 + tx*4];
        float madd[4] = {(1.f-mk.x)*(-1e6f), (1.f-mk.y)*(-1e6f),
                         (1.f-mk.z)*(-1e6f), (1.f-mk.w)*(-1e6f)};

#pragma unroll
        for (int i = 0; i < 4; i++) {
            const int row = ty*4 + i;
            float sv[4];
            unpack2(acc[i][0], sv[0], sv[1]);
            unpack2(acc[i][1], sv[2], sv[3]);
            float4 bb = *(const float4*)&g_bias[bh + (size_t)(i0+row)*NN + j0 + tx*4];
            sv[0] = fmaf(sv[0], scale, bb.x + madd[0]);
            sv[1] = fmaf(sv[1], scale, bb.y + madd[1]);
            sv[2] = fmaf(sv[2], scale, bb.z + madd[2]);
            sv[3] = fmaf(sv[3], scale, bb.w + madd[3]);

            float rm = fmaxf(fmaxf(sv[0], sv[1]), fmaxf(sv[2], sv[3]));
            rm = shfl_max16(rm);
            float mn = fmaxf(mrow[i], rm);
            float p0 = __expf(sv[0] - mn), p1 = __expf(sv[1] - mn);
            float p2 = __expf(sv[2] - mn), p3 = __expf(sv[3] - mn);
            float rs = shfl_sum16(p0 + p1 + p2 + p3);
            float sc = __expf(mrow[i] - mn);
            lrow[i] = lrow[i] * sc + rs;
            mrow[i] = mn;
            *(float4*)&ps[row*PSS + tx*4] = make_float4(p0, p1, p2, p3);
            if (tx == 0) scale_s[row] = sc;
        }
        __syncthreads();

        {
            const int r0 = ty2*2, r1 = ty2*2 + 1;
            ull d0 = dup2(scale_s[r0]);
            ull d1 = dup2(scale_s[r1]);
#pragma unroll
            for (int c = 0; c < 3; c++) { mul2(oacc[0][c], d0); mul2(oacc[1][c], d1); }

            const float* vbase = vs + tx2*6;
#pragma unroll 4
            for (int k = 0; k < JT; k += 2) {
                ull pk0 = *(const ull*)&ps[r0*PSS + k];
                ull pk1 = *(const ull*)&ps[r1*PSS + k];
                float p00, p01, p10, p11;
                unpack2(pk0, p00, p01);
                unpack2(pk1, p10, p11);
                const float* v0 = vbase + k*48;
                const float* v1 = v0 + 48;
                ull va0 = *(const ull*)(v0);
                ull va1 = *(const ull*)(v0 + 2);
                ull va2 = *(const ull*)(v0 + 4);
                ull vb0 = *(const ull*)(v1);
                ull vb1 = *(const ull*)(v1 + 2);
                ull vb2 = *(const ull*)(v1 + 4);
                ull a00 = dup2(p00), a10 = dup2(p10);
                fma2(oacc[0][0], a00, va0); fma2(oacc[0][1], a00, va1); fma2(oacc[0][2], a00, va2);
                fma2(oacc[1][0], a10, va0); fma2(oacc[1][1], a10, va1); fma2(oacc[1][2], a10, va2);
                ull a01 = dup2(p01), a11 = dup2(p11);
                fma2(oacc[0][0], a01, vb0); fma2(oacc[0][1], a01, vb1); fma2(oacc[0][2], a01, vb2);
                fma2(oacc[1][0], a11, vb0); fma2(oacc[1][1], a11, vb1); fma2(oacc[1][2], a11, vb2);
            }
        }
    }

    if (tx == 0) {
#pragma unroll
        for (int i = 0; i < 4; i++) l_s[ty*4 + i] = lrow[i];
    }
    __syncthreads();

#pragma unroll
    for (int r = 0; r < 2; r++) {
        const int row = ty2*2 + r;
        const float inv = 1.f / l_s[row];
        const size_t off = ((size_t)(b*NN + i0 + row))*CS + h*HD + tx2*6;
#pragma unroll
        for (int c = 0; c < 3; c++) {
            float o0, o1;
            unpack2(oacc[r][c], o0, o1);
            float gg0 = g_g[off + 2*c], gg1 = g_g[off + 2*c + 1];
            *(ull*)&g_og[off + 2*c] = pack2(o0 * inv * gg0, o1 * inv * gg1);
        }
    }
}

extern "C" void kernel_launch(void* const* d_in, const int* in_sizes, int n_in,
                              void* d_out, int out_size)
{
    const float* s    = (const float*)d_in[0];
    const float* z    = (const float*)d_in[1];
    const float* mask = (const float*)d_in[2];
    const float* kin  = (const float*)d_in[3];
    const float* Wq   = (const float*)d_in[4];
    const float* bq   = (const float*)d_in[5];
    const float* Wk   = (const float*)d_in[6];
    const float* Wv   = (const float*)d_in[7];
    const float* Wg   = (const float*)d_in[8];
    const float* lng  = (const float*)d_in[9];
    const float* lnb  = (const float*)d_in[10];
    const float* Wz   = (const float*)d_in[11];
    const float* Wo   = (const float*)d_in[12];
    float* out = (float*)d_out;

    const int attn_smem = (48*IT + 48*JT + JT*48 + IT*PSS + IT + IT) * 4;
    cudaFuncSetAttribute(attn_kernel,
                         cudaFuncAttributeMaxDynamicSharedMemorySize, attn_smem);

    // fork: biasproj (DRAM-bound) concurrent with qkvg (fma-bound).
    // stream/events intentionally leaked (destroy during capture invalidates it).
    cudaStream_t s2;
    cudaStreamCreateWithFlags(&s2, cudaStreamNonBlocking);
    cudaEvent_t eFork, eJoin;
    cudaEventCreateWithFlags(&eFork, cudaEventDisableTiming);
    cudaEventCreateWithFlags(&eJoin, cudaEventDisableTiming);

    cudaEventRecord(eFork, 0);
    cudaStreamWaitEvent(s2, eFork, 0);

    qkvg_kernel<<<dim3(CS/128, BB*NN/128, 4), 256>>>(s, kin, Wq, bq, Wk, Wv, Wg);
    biasproj_kernel<<<BB*NN*NN/256, 256, 0, s2>>>(z, lng, lnb, Wz);

    cudaEventRecord(eJoin, s2);
    cudaStreamWaitEvent(0, eJoin, 0);

    attn_kernel<<<dim3(NN/IT, BB*HH), 256, attn_smem>>>(mask);
    outproj_partial_kernel<<<dim3(CS/128, BB*NN/128, 4), 256>>>(Wo);
    reduce4_kernel<<<(BB*NN*CS/4)/256, 256>>>(out);
}